// round 2
// baseline (speedup 1.0000x reference)
#include <cuda_runtime.h>
#include <math.h>

#define NB   32
#define RESO 256
#define KK   1024
#define EPSF 1e-6f

// Scratch (no allocations allowed): sampled control points + accumulators.
__device__ float2 g_src[NB * KK];
__device__ float2 g_trg[NB * KK];
__device__ double g_loss;
__device__ double g_vis;

// ---------------------------------------------------------------------------
// Kernel 1: bilinear sampling of src_flow@src_kp and trg_flow@trg_kp.
// 2*N*K = 65536 threads. Also zeroes the global accumulators (tid 0).
// ---------------------------------------------------------------------------
__global__ void sample_kernel(const float* __restrict__ src_flow,
                              const float* __restrict__ trg_flow,
                              const float* __restrict__ src_kp,
                              const float* __restrict__ trg_kp) {
    int tid = blockIdx.x * blockDim.x + threadIdx.x;
    if (tid == 0) { g_loss = 0.0; g_vis = 0.0; }
    if (tid >= 2 * NB * KK) return;

    int sel = tid >= NB * KK;          // 0 = src, 1 = trg
    int idx = sel ? (tid - NB * KK) : tid;
    const float* flow = sel ? trg_flow : src_flow;
    const float* kp   = sel ? trg_kp   : src_kp;

    float x = kp[idx * 2 + 0];
    float y = kp[idx * 2 + 1];
    int   n = idx / KK;

    float x0f = floorf(x), y0f = floorf(y);
    int   x0  = (int)x0f,  y0  = (int)y0f;
    float wx  = x - x0f,   wy  = y - y0f;

    const float* base = flow + (size_t)n * RESO * RESO * 2;

    auto gather = [&](int xi, int yi, float& a, float& b) {
        if (xi >= 0 && xi < RESO && yi >= 0 && yi < RESO) {
            const float2 v = *reinterpret_cast<const float2*>(base + ((size_t)yi * RESO + xi) * 2);
            a = v.x; b = v.y;
        } else { a = 0.f; b = 0.f; }
    };

    float a00, b00, a10, b10, a01, b01, a11, b11;
    gather(x0,     y0,     a00, b00);
    gather(x0 + 1, y0,     a10, b10);
    gather(x0,     y0 + 1, a01, b01);
    gather(x0 + 1, y0 + 1, a11, b11);

    float w00 = (1.f - wx) * (1.f - wy);
    float w10 = wx * (1.f - wy);
    float w01 = (1.f - wx) * wy;
    float w11 = wx * wy;

    float2 r;
    r.x = a00 * w00 + a10 * w10 + a01 * w01 + a11 * w11;
    r.y = b00 * w00 + b10 * w10 + b01 * w01 + b11 * w11;

    if (sel) g_trg[idx] = r; else g_src[idx] = r;
}

// ---------------------------------------------------------------------------
// Kernel 2: per (n, j): ce = log( sum_i exp(-dist(src_i, trg_j)) ) + dist_jj.
// d1 and d2 in the reference are numerically identical -> contribution is
// 2 * ce * vis * wt. Block = 64 threads (one j each), grid = (K/64, N).
// src_c[n,:] cached in shared memory; MUFU-bound inner loop with 4
// independent accumulators for ILP.
// ---------------------------------------------------------------------------
__global__ void __launch_bounds__(64) loss_kernel(const int* __restrict__ kp_vis,
                                                  const float* __restrict__ kp_wt) {
    __shared__ float2 s_src[KK];
    const int n = blockIdx.y;
    const int j = blockIdx.x * 64 + threadIdx.x;

    const float2* srcn = g_src + n * KK;
    #pragma unroll
    for (int i = threadIdx.x; i < KK; i += 64) s_src[i] = srcn[i];
    __syncthreads();

    const float2 t  = g_trg[n * KK + j];
    const float txe = t.x - EPSF;   // dx = sx - tx + eps = sx - txe
    const float tye = t.y - EPSF;

    const float NLOG2E = -1.4426950408889634f; // exp(-d) = exp2(-d*log2e)

    float acc0 = 0.f, acc1 = 0.f, acc2 = 0.f, acc3 = 0.f;
    #pragma unroll 2
    for (int i = 0; i < KK; i += 4) {
        float2 s0 = s_src[i + 0];
        float2 s1 = s_src[i + 1];
        float2 s2 = s_src[i + 2];
        float2 s3 = s_src[i + 3];

        float dx0 = s0.x - txe, dy0 = s0.y - tye;
        float dx1 = s1.x - txe, dy1 = s1.y - tye;
        float dx2 = s2.x - txe, dy2 = s2.y - tye;
        float dx3 = s3.x - txe, dy3 = s3.y - tye;

        float q0 = fmaxf(fmaf(dy0, dy0, dx0 * dx0), 1e-30f);
        float q1 = fmaxf(fmaf(dy1, dy1, dx1 * dx1), 1e-30f);
        float q2 = fmaxf(fmaf(dy2, dy2, dx2 * dx2), 1e-30f);
        float q3 = fmaxf(fmaf(dy3, dy3, dx3 * dx3), 1e-30f);

        float d0 = q0 * __frsqrt_rn(q0);   // sqrt via MUFU.RSQ + FMUL
        float d1 = q1 * __frsqrt_rn(q1);
        float d2 = q2 * __frsqrt_rn(q2);
        float d3 = q3 * __frsqrt_rn(q3);

        acc0 += exp2f(d0 * NLOG2E);        // MUFU.EX2
        acc1 += exp2f(d1 * NLOG2E);
        acc2 += exp2f(d2 * NLOG2E);
        acc3 += exp2f(d3 * NLOG2E);
    }
    float acc = (acc0 + acc1) + (acc2 + acc3);

    // diagonal distance dist(src_j, trg_j)
    float2 sj = s_src[j];
    float dxj = sj.x - txe, dyj = sj.y - tye;
    float djj = sqrtf(fmaf(dyj, dyj, dxj * dxj));

    float ce = logf(acc) + djj;

    // kp_vis: bool materialized as a 32-bit type (int32 0/1 or float32 0.0/1.0).
    // Nonzero-word test is correct for both encodings.
    int vis = (kp_vis[n * KK + j] != 0);
    float wt = kp_wt[n * KK + j];
    float contrib = vis ? 2.0f * ce * wt : 0.0f;
    float viscnt  = vis ? 1.0f : 0.0f;

    // block reduce (2 warps)
    #pragma unroll
    for (int o = 16; o > 0; o >>= 1) {
        contrib += __shfl_down_sync(0xffffffffu, contrib, o);
        viscnt  += __shfl_down_sync(0xffffffffu, viscnt,  o);
    }
    __shared__ float s_v[2], s_c[2];
    if ((threadIdx.x & 31) == 0) {
        s_v[threadIdx.x >> 5] = contrib;
        s_c[threadIdx.x >> 5] = viscnt;
    }
    __syncthreads();
    if (threadIdx.x == 0) {
        atomicAdd(&g_loss, (double)(s_v[0] + s_v[1]));
        atomicAdd(&g_vis,  (double)(s_c[0] + s_c[1]));
    }
}

// ---------------------------------------------------------------------------
// Kernel 3: final divide.
// ---------------------------------------------------------------------------
__global__ void finalize_kernel(float* __restrict__ out) {
    out[0] = (float)(g_loss / g_vis);
}

extern "C" void kernel_launch(void* const* d_in, const int* in_sizes, int n_in,
                              void* d_out, int out_size) {
    const float* src_flow = (const float*)d_in[0];
    const float* trg_flow = (const float*)d_in[1];
    const float* src_kp   = (const float*)d_in[2];
    const float* trg_kp   = (const float*)d_in[3];
    const int*   kp_vis   = (const int*)d_in[4];
    const float* kp_wt    = (const float*)d_in[5];
    float* out = (float*)d_out;

    // K1: sampling + accumulator reset. 2*N*K threads.
    sample_kernel<<<(2 * NB * KK + 255) / 256, 256>>>(src_flow, trg_flow, src_kp, trg_kp);

    // K2: pairwise LSE + diag + weighted reduction. 512 blocks x 64 threads.
    dim3 grid(KK / 64, NB);
    loss_kernel<<<grid, 64>>>(kp_vis, kp_wt);

    // K3: scalar divide.
    finalize_kernel<<<1, 1>>>(out);
}

// round 4
// speedup vs baseline: 2.7391x; 2.7391x over previous
#include <cuda_runtime.h>
#include <math.h>

#define NB   32
#define RESO 256
#define KK   1024
#define EPSF 1e-6f
#define ISPLIT 4
#define ICHUNK (KK / ISPLIT)   // 256

// Scratch (no allocations allowed).
__device__ float4 g_src4[NB * KK];   // (sx, sy, sx^2+sy^2, 0)
__device__ float4 g_trg4[NB * KK];   // (tx', ty', tx'^2+ty'^2, 0) with t' = t - eps
__device__ float  g_part[ISPLIT * NB * KK];  // partial exp-sums
__device__ double g_loss;
__device__ double g_vis;

__device__ __forceinline__ float rsq_approx(float x) {
    float r; asm("rsqrt.approx.f32 %0, %1;" : "=f"(r) : "f"(x)); return r;
}
__device__ __forceinline__ float ex2_approx(float x) {
    float r; asm("ex2.approx.f32 %0, %1;" : "=f"(r) : "f"(x)); return r;
}
__device__ __forceinline__ float lg2_approx(float x) {
    float r; asm("lg2.approx.f32 %0, %1;" : "=f"(r) : "f"(x)); return r;
}

// ---------------------------------------------------------------------------
// Kernel 1: bilinear sampling; emits packed float4 per point.
// ---------------------------------------------------------------------------
__global__ void sample_kernel(const float* __restrict__ src_flow,
                              const float* __restrict__ trg_flow,
                              const float* __restrict__ src_kp,
                              const float* __restrict__ trg_kp) {
    int tid = blockIdx.x * blockDim.x + threadIdx.x;
    if (tid == 0) { g_loss = 0.0; g_vis = 0.0; }
    if (tid >= 2 * NB * KK) return;

    int sel = tid >= NB * KK;          // 0 = src, 1 = trg
    int idx = sel ? (tid - NB * KK) : tid;
    const float* flow = sel ? trg_flow : src_flow;
    const float* kp   = sel ? trg_kp   : src_kp;

    float x = kp[idx * 2 + 0];
    float y = kp[idx * 2 + 1];
    int   n = idx / KK;

    float x0f = floorf(x), y0f = floorf(y);
    int   x0  = (int)x0f,  y0  = (int)y0f;
    float wx  = x - x0f,   wy  = y - y0f;

    const float* base = flow + (size_t)n * RESO * RESO * 2;

    auto gather = [&](int xi, int yi, float& a, float& b) {
        if (xi >= 0 && xi < RESO && yi >= 0 && yi < RESO) {
            const float2 v = *reinterpret_cast<const float2*>(base + ((size_t)yi * RESO + xi) * 2);
            a = v.x; b = v.y;
        } else { a = 0.f; b = 0.f; }
    };

    float a00, b00, a10, b10, a01, b01, a11, b11;
    gather(x0,     y0,     a00, b00);
    gather(x0 + 1, y0,     a10, b10);
    gather(x0,     y0 + 1, a01, b01);
    gather(x0 + 1, y0 + 1, a11, b11);

    float w00 = (1.f - wx) * (1.f - wy);
    float w10 = wx * (1.f - wy);
    float w01 = (1.f - wx) * wy;
    float w11 = wx * wy;

    float cx = a00 * w00 + a10 * w10 + a01 * w01 + a11 * w11;
    float cy = b00 * w00 + b10 * w10 + b01 * w01 + b11 * w11;

    if (sel) {
        float txe = cx - EPSF, tye = cy - EPSF;
        g_trg4[idx] = make_float4(txe, tye, txe * txe + tye * tye, 0.f);
    } else {
        g_src4[idx] = make_float4(cx, cy, cx * cx + cy * cy, 0.f);
    }
}

// ---------------------------------------------------------------------------
// Kernel 2: partial exp-sums. Per (n, j, split):
//   part = sum_{i in chunk} exp(-sqrt(|s_i|^2 - 2 s_i . t'_j + |t'_j|^2))
// grid = (K/64, N, ISPLIT), block = 64. smem caches 256 src float4 (4 KB).
// Inner loop: MUFU-bound (RSQ + EX2 per pair), minimal FMA-pipe work.
// ---------------------------------------------------------------------------
__global__ void __launch_bounds__(64) loss_partial_kernel() {
    __shared__ float4 s_src[ICHUNK];
    const int n     = blockIdx.y;
    const int split = blockIdx.z;
    const int j     = blockIdx.x * 64 + threadIdx.x;

    const float4* srcn = g_src4 + n * KK + split * ICHUNK;
    #pragma unroll
    for (int i = threadIdx.x; i < ICHUNK; i += 64) s_src[i] = srcn[i];
    __syncthreads();

    const float4 t = g_trg4[n * KK + j];
    const float a  = -2.0f * t.x;
    const float b  = -2.0f * t.y;
    const float tt = t.z;

    const float NLOG2E = -1.4426950408889634f;

    float acc0 = 0.f, acc1 = 0.f, acc2 = 0.f, acc3 = 0.f;
    #pragma unroll 2
    for (int i = 0; i < ICHUNK; i += 4) {
        float4 s0 = s_src[i + 0];
        float4 s1 = s_src[i + 1];
        float4 s2 = s_src[i + 2];
        float4 s3 = s_src[i + 3];

        float q0 = fmaf(s0.x, a, fmaf(s0.y, b, s0.z + tt));
        float q1 = fmaf(s1.x, a, fmaf(s1.y, b, s1.z + tt));
        float q2 = fmaf(s2.x, a, fmaf(s2.y, b, s2.z + tt));
        float q3 = fmaf(s3.x, a, fmaf(s3.y, b, s3.z + tt));

        q0 = fmaxf(q0, 1e-30f);
        q1 = fmaxf(q1, 1e-30f);
        q2 = fmaxf(q2, 1e-30f);
        q3 = fmaxf(q3, 1e-30f);

        float r0 = rsq_approx(q0);
        float r1 = rsq_approx(q1);
        float r2 = rsq_approx(q2);
        float r3 = rsq_approx(q3);

        // e = -log2e * sqrt(q) = (q * NLOG2E) * rsq(q)
        float e0 = (q0 * NLOG2E) * r0;
        float e1 = (q1 * NLOG2E) * r1;
        float e2 = (q2 * NLOG2E) * r2;
        float e3 = (q3 * NLOG2E) * r3;

        acc0 += ex2_approx(e0);
        acc1 += ex2_approx(e1);
        acc2 += ex2_approx(e2);
        acc3 += ex2_approx(e3);
    }
    g_part[(split * NB + n) * KK + j] = (acc0 + acc1) + (acc2 + acc3);
}

// ---------------------------------------------------------------------------
// Kernel 3: per (n,j): ce = log(sum parts) + dist_jj; weight, reduce.
// grid = N, block = K.
// ---------------------------------------------------------------------------
__global__ void __launch_bounds__(KK) reduce_kernel(const int* __restrict__ kp_vis,
                                                    const float* __restrict__ kp_wt) {
    const int n = blockIdx.x;
    const int j = threadIdx.x;

    float acc = 0.f;
    #pragma unroll
    for (int s = 0; s < ISPLIT; s++) acc += g_part[(s * NB + n) * KK + j];

    float4 sj = g_src4[n * KK + j];
    float4 tj = g_trg4[n * KK + j];
    float dx = sj.x - tj.x, dy = sj.y - tj.y;
    float qd = fmaxf(fmaf(dy, dy, dx * dx), 1e-30f);
    float djj = qd * rsq_approx(qd);

    const float LN2 = 0.6931471805599453f;
    float ce = lg2_approx(acc) * LN2 + djj;

    int   vis = (kp_vis[n * KK + j] != 0);
    float wt  = kp_wt[n * KK + j];
    float contrib = vis ? 2.0f * ce * wt : 0.0f;
    float viscnt  = vis ? 1.0f : 0.0f;

    #pragma unroll
    for (int o = 16; o > 0; o >>= 1) {
        contrib += __shfl_down_sync(0xffffffffu, contrib, o);
        viscnt  += __shfl_down_sync(0xffffffffu, viscnt,  o);
    }
    __shared__ float s_v[32], s_c[32];
    int wid = j >> 5, lid = j & 31;
    if (lid == 0) { s_v[wid] = contrib; s_c[wid] = viscnt; }
    __syncthreads();
    if (wid == 0) {
        float v = s_v[lid], c = s_c[lid];
        #pragma unroll
        for (int o = 16; o > 0; o >>= 1) {
            v += __shfl_down_sync(0xffffffffu, v, o);
            c += __shfl_down_sync(0xffffffffu, c, o);
        }
        if (lid == 0) {
            atomicAdd(&g_loss, (double)v);
            atomicAdd(&g_vis,  (double)c);
        }
    }
}

// ---------------------------------------------------------------------------
// Kernel 4: final divide.
// ---------------------------------------------------------------------------
__global__ void finalize_kernel(float* __restrict__ out) {
    out[0] = (float)(g_loss / g_vis);
}

extern "C" void kernel_launch(void* const* d_in, const int* in_sizes, int n_in,
                              void* d_out, int out_size) {
    const float* src_flow = (const float*)d_in[0];
    const float* trg_flow = (const float*)d_in[1];
    const float* src_kp   = (const float*)d_in[2];
    const float* trg_kp   = (const float*)d_in[3];
    const int*   kp_vis   = (const int*)d_in[4];
    const float* kp_wt    = (const float*)d_in[5];
    float* out = (float*)d_out;

    sample_kernel<<<(2 * NB * KK + 255) / 256, 256>>>(src_flow, trg_flow, src_kp, trg_kp);

    dim3 grid(KK / 64, NB, ISPLIT);
    loss_partial_kernel<<<grid, 64>>>();

    reduce_kernel<<<NB, KK>>>(kp_vis, kp_wt);

    finalize_kernel<<<1, 1>>>(out);
}

// round 5
// speedup vs baseline: 2.8094x; 1.0256x over previous
#include <cuda_runtime.h>
#include <math.h>

#define NB   32
#define RESO 256
#define KK   1024
#define EPSF 1e-6f
#define ISPLIT 4
#define ICHUNK (KK / ISPLIT)   // 256

// Scratch (no allocations allowed).
__device__ float4 g_src4[NB * KK];   // (sx, sy, sx^2+sy^2, 0)
__device__ float4 g_trg4[NB * KK];   // (tx', ty', tx'^2+ty'^2, 0) with t' = t - eps
__device__ float  g_part[ISPLIT * NB * KK];  // partial exp-sums
__device__ double g_loss;
__device__ double g_vis;
__device__ unsigned int g_done;

__device__ __forceinline__ float sqrt_approx(float x) {
    float r; asm("sqrt.approx.f32 %0, %1;" : "=f"(r) : "f"(x)); return r;
}
__device__ __forceinline__ float ex2_approx(float x) {
    float r; asm("ex2.approx.f32 %0, %1;" : "=f"(r) : "f"(x)); return r;
}
__device__ __forceinline__ float lg2_approx(float x) {
    float r; asm("lg2.approx.f32 %0, %1;" : "=f"(r) : "f"(x)); return r;
}

// ---------------------------------------------------------------------------
// Kernel 1: bilinear sampling; emits packed float4 per point.
// Unconditional clamped loads (4-deep MLP) with validity mask multiply.
// Also resets the accumulators and the completion counter.
// ---------------------------------------------------------------------------
__global__ void sample_kernel(const float* __restrict__ src_flow,
                              const float* __restrict__ trg_flow,
                              const float* __restrict__ src_kp,
                              const float* __restrict__ trg_kp) {
    int tid = blockIdx.x * blockDim.x + threadIdx.x;
    if (tid == 0) { g_loss = 0.0; g_vis = 0.0; g_done = 0u; }
    if (tid >= 2 * NB * KK) return;

    int sel = tid >= NB * KK;          // 0 = src, 1 = trg
    int idx = sel ? (tid - NB * KK) : tid;
    const float* flow = sel ? trg_flow : src_flow;
    const float2 p = reinterpret_cast<const float2*>(sel ? trg_kp : src_kp)[idx];

    int   n = idx / KK;

    float x0f = floorf(p.x), y0f = floorf(p.y);
    int   x0  = (int)x0f,    y0  = (int)y0f;
    float wx  = p.x - x0f,   wy  = p.y - y0f;
    int   x1  = x0 + 1,      y1  = y0 + 1;

    // clamped coords (always in-bounds -> unconditional loads)
    int x0c = min(max(x0, 0), RESO - 1);
    int x1c = min(max(x1, 0), RESO - 1);
    int y0c = min(max(y0, 0), RESO - 1);
    int y1c = min(max(y1, 0), RESO - 1);

    float vx0 = (x0 >= 0 && x0 < RESO) ? 1.f : 0.f;
    float vx1 = (x1 >= 0 && x1 < RESO) ? 1.f : 0.f;
    float vy0 = (y0 >= 0 && y0 < RESO) ? 1.f : 0.f;
    float vy1 = (y1 >= 0 && y1 < RESO) ? 1.f : 0.f;

    const float2* base = reinterpret_cast<const float2*>(flow) + (size_t)n * RESO * RESO;

    // four independent loads, issued back-to-back
    float2 v00 = base[y0c * RESO + x0c];
    float2 v10 = base[y0c * RESO + x1c];
    float2 v01 = base[y1c * RESO + x0c];
    float2 v11 = base[y1c * RESO + x1c];

    float w00 = (1.f - wx) * (1.f - wy) * vx0 * vy0;
    float w10 = wx * (1.f - wy) * vx1 * vy0;
    float w01 = (1.f - wx) * wy * vx0 * vy1;
    float w11 = wx * wy * vx1 * vy1;

    float cx = v00.x * w00 + v10.x * w10 + v01.x * w01 + v11.x * w11;
    float cy = v00.y * w00 + v10.y * w10 + v01.y * w01 + v11.y * w11;

    if (sel) {
        float txe = cx - EPSF, tye = cy - EPSF;
        g_trg4[idx] = make_float4(txe, tye, txe * txe + tye * tye, 0.f);
    } else {
        g_src4[idx] = make_float4(cx, cy, cx * cx + cy * cy, 0.f);
    }
}

// ---------------------------------------------------------------------------
// Kernel 2: partial exp-sums. Per (n, j, split):
//   part = sum_{i in chunk} exp(-sqrt(|s_i|^2 - 2 s_i . t'_j + |t'_j|^2))
// grid = (K/64, N, ISPLIT), block = 64. MUFU-bound (SQRT + EX2 per pair).
// ---------------------------------------------------------------------------
__global__ void __launch_bounds__(64) loss_partial_kernel() {
    __shared__ float4 s_src[ICHUNK];
    const int n     = blockIdx.y;
    const int split = blockIdx.z;
    const int j     = blockIdx.x * 64 + threadIdx.x;

    const float4* srcn = g_src4 + n * KK + split * ICHUNK;
    #pragma unroll
    for (int i = threadIdx.x; i < ICHUNK; i += 64) s_src[i] = srcn[i];
    __syncthreads();

    const float4 t = g_trg4[n * KK + j];
    const float a  = -2.0f * t.x;
    const float b  = -2.0f * t.y;
    const float tt = t.z;

    const float NLOG2E = -1.4426950408889634f;

    float acc0 = 0.f, acc1 = 0.f, acc2 = 0.f, acc3 = 0.f;
    #pragma unroll 2
    for (int i = 0; i < ICHUNK; i += 4) {
        float4 s0 = s_src[i + 0];
        float4 s1 = s_src[i + 1];
        float4 s2 = s_src[i + 2];
        float4 s3 = s_src[i + 3];

        float q0 = fmaf(s0.x, a, fmaf(s0.y, b, s0.z + tt));
        float q1 = fmaf(s1.x, a, fmaf(s1.y, b, s1.z + tt));
        float q2 = fmaf(s2.x, a, fmaf(s2.y, b, s2.z + tt));
        float q3 = fmaf(s3.x, a, fmaf(s3.y, b, s3.z + tt));

        q0 = fmaxf(q0, 1e-30f);
        q1 = fmaxf(q1, 1e-30f);
        q2 = fmaxf(q2, 1e-30f);
        q3 = fmaxf(q3, 1e-30f);

        float d0 = sqrt_approx(q0);
        float d1 = sqrt_approx(q1);
        float d2 = sqrt_approx(q2);
        float d3 = sqrt_approx(q3);

        acc0 += ex2_approx(d0 * NLOG2E);
        acc1 += ex2_approx(d1 * NLOG2E);
        acc2 += ex2_approx(d2 * NLOG2E);
        acc3 += ex2_approx(d3 * NLOG2E);
    }
    g_part[(split * NB + n) * KK + j] = (acc0 + acc1) + (acc2 + acc3);
}

// ---------------------------------------------------------------------------
// Kernel 3: per (n,j): ce = log(sum parts) + dist_jj; weight, reduce.
// grid = N, block = K. The LAST finishing block also writes the final result
// (counter + threadfence; accumulator re-read via atomicAdd(+0) to bypass L1).
// ---------------------------------------------------------------------------
__global__ void __launch_bounds__(KK) reduce_kernel(const int* __restrict__ kp_vis,
                                                    const float* __restrict__ kp_wt,
                                                    float* __restrict__ out) {
    const int n = blockIdx.x;
    const int j = threadIdx.x;

    float acc = 0.f;
    #pragma unroll
    for (int s = 0; s < ISPLIT; s++) acc += g_part[(s * NB + n) * KK + j];

    float4 sj = g_src4[n * KK + j];
    float4 tj = g_trg4[n * KK + j];
    float dx = sj.x - tj.x, dy = sj.y - tj.y;
    float qd = fmaxf(fmaf(dy, dy, dx * dx), 1e-30f);
    float djj = sqrt_approx(qd);

    const float LN2 = 0.6931471805599453f;
    float ce = lg2_approx(acc) * LN2 + djj;

    int   vis = (kp_vis[n * KK + j] != 0);
    float wt  = kp_wt[n * KK + j];
    float contrib = vis ? 2.0f * ce * wt : 0.0f;
    float viscnt  = vis ? 1.0f : 0.0f;

    #pragma unroll
    for (int o = 16; o > 0; o >>= 1) {
        contrib += __shfl_down_sync(0xffffffffu, contrib, o);
        viscnt  += __shfl_down_sync(0xffffffffu, viscnt,  o);
    }
    __shared__ float s_v[32], s_c[32];
    int wid = j >> 5, lid = j & 31;
    if (lid == 0) { s_v[wid] = contrib; s_c[wid] = viscnt; }
    __syncthreads();
    if (j == 0) {
        float v = 0.f, c = 0.f;
        #pragma unroll
        for (int w = 0; w < 32; w++) { v += s_v[w]; c += s_c[w]; }
        atomicAdd(&g_loss, (double)v);
        atomicAdd(&g_vis,  (double)c);
        __threadfence();
        unsigned int done = atomicAdd(&g_done, 1u);
        if (done == NB - 1) {
            // all blocks' accumulator updates are visible now
            double L = atomicAdd(&g_loss, 0.0);
            double V = atomicAdd(&g_vis, 0.0);
            out[0] = (float)(L / V);
        }
    }
}

extern "C" void kernel_launch(void* const* d_in, const int* in_sizes, int n_in,
                              void* d_out, int out_size) {
    const float* src_flow = (const float*)d_in[0];
    const float* trg_flow = (const float*)d_in[1];
    const float* src_kp   = (const float*)d_in[2];
    const float* trg_kp   = (const float*)d_in[3];
    const int*   kp_vis   = (const int*)d_in[4];
    const float* kp_wt    = (const float*)d_in[5];
    float* out = (float*)d_out;

    sample_kernel<<<(2 * NB * KK + 255) / 256, 256>>>(src_flow, trg_flow, src_kp, trg_kp);

    dim3 grid(KK / 64, NB, ISPLIT);
    loss_partial_kernel<<<grid, 64>>>();

    reduce_kernel<<<NB, KK>>>(kp_vis, kp_wt, out);
}